// round 1
// baseline (speedup 1.0000x reference)
#include <cuda_runtime.h>
#include <cuda_bf16.h>
#include <cstdint>

// LengthRegulator: the reference's duration-predictor output is DEAD CODE
// (durations = target_durations overrides it). Live work:
//   cum = cumsum(target_durations, axis=1)
//   padded[b,f,:] = (f < cum[b,-1]) ? x[b, upper_bound(cum[b], f), :] : 0
//   durations_out = target_durations
//
// Shapes: B=8, T=1024, D=1024, F = T*DMAX = 8192.
// Output buffer (concatenated, fp32): [B*F*D padded][B*T durations].

#define LR_B 8
#define LR_T 1024
#define LR_D 1024
#define LR_F 8192   // T * DMAX

// frame -> token map, -1 == invalid (zero-fill) frame
__device__ int g_tok[LR_B * LR_F];

// ---------------------------------------------------------------------------
// Kernel 1: per-batch inclusive scan of durations + scatter frame->token map.
// One block per batch row, 1024 threads (one per token).
// ---------------------------------------------------------------------------
__global__ void lr_build_map_kernel(const int* __restrict__ dur) {
    __shared__ int s[LR_T];
    const int b = blockIdx.x;
    const int t = threadIdx.x;

    s[t] = dur[b * LR_T + t];
    __syncthreads();

    // Hillis-Steele inclusive scan over 1024 elements (10 steps)
    #pragma unroll
    for (int off = 1; off < LR_T; off <<= 1) {
        int v   = s[t];
        int add = (t >= off) ? s[t - off] : 0;
        __syncthreads();
        s[t] = v + add;
        __syncthreads();
    }

    const int total = s[LR_T - 1];

    // Mark invalid frames (>= total) with -1. Valid region is fully covered
    // by the scatter below (disjoint ranges), so no overlap.
    for (int f = t; f < LR_F; f += LR_T) {
        if (f >= total) g_tok[b * LR_F + f] = -1;
    }

    // Scatter: token t owns frames [cum[t-1], cum[t])
    const int end   = s[t];
    const int start = (t == 0) ? 0 : s[t - 1];
    for (int f = start; f < end; ++f) {
        g_tok[b * LR_F + f] = t;
    }
}

// ---------------------------------------------------------------------------
// Kernel 2: expand. One block per output frame row (grid 8192 x 8),
// 256 threads, one float4 (16B) per thread -> 4KB row copy or zero-fill.
// ---------------------------------------------------------------------------
__global__ void lr_expand_kernel(const float* __restrict__ x,
                                 float* __restrict__ out) {
    const int f = blockIdx.x;
    const int b = blockIdx.y;
    const int tok = g_tok[b * LR_F + f];  // uniform across block, L1/L2 hit

    float4* orow = reinterpret_cast<float4*>(out) +
                   ((size_t)b * LR_F + f) * (LR_D / 4);
    const int i = threadIdx.x;  // 0..255 == D/4

    if (tok < 0) {
        orow[i] = make_float4(0.f, 0.f, 0.f, 0.f);
    } else {
        const float4* src = reinterpret_cast<const float4*>(x) +
                            ((size_t)b * LR_T + tok) * (LR_D / 4);
        orow[i] = src[i];
    }
}

// ---------------------------------------------------------------------------
// Kernel 3: durations pass-through (int -> float) appended after padded.
// ---------------------------------------------------------------------------
__global__ void lr_durations_kernel(const int* __restrict__ dur,
                                    float* __restrict__ out) {
    const int i = blockIdx.x * blockDim.x + threadIdx.x;
    if (i < LR_B * LR_T) out[i] = (float)dur[i];
}

extern "C" void kernel_launch(void* const* d_in, const int* in_sizes, int n_in,
                              void* d_out, int out_size) {
    const float* x   = (const float*)d_in[0];  // [B, T, D] fp32
    const int*   dur = (const int*)  d_in[1];  // [B, T] int32
    float* out = (float*)d_out;

    // 1) frame->token map
    lr_build_map_kernel<<<LR_B, LR_T>>>(dur);

    // 2) gather/expand into padded output
    dim3 grid(LR_F, LR_B);
    lr_expand_kernel<<<grid, LR_D / 4>>>(x, out);

    // 3) durations tail (only if the harness buffer includes it)
    const long long padded_elems = (long long)LR_B * LR_F * LR_D;
    if ((long long)out_size >= padded_elems + (long long)LR_B * LR_T) {
        lr_durations_kernel<<<(LR_B * LR_T + 255) / 256, 256>>>(
            dur, out + padded_elems);
    }
}

// round 2
// speedup vs baseline: 1.0595x; 1.0595x over previous
#include <cuda_runtime.h>
#include <cuda_bf16.h>
#include <cstdint>

// LengthRegulator: predictor is dead code in the reference (durations =
// target_durations). Live work:
//   cum = cumsum(target_durations, axis=1)
//   padded[b,f,:] = (f < cum[b,-1]) ? x[b, upper_bound(cum[b], f), :] : 0
//   durations_out = target_durations
//
// B=8, T=1024, D=1024, F=8192. Output fp32: [B*F*D padded][B*T durations].
//
// R2 strategy: token-major expand (read each x row ONCE, write it dur times)
// + fused zero-fill, warp-shuffle scan with fused durations pass-through.

#define LR_B 8
#define LR_T 1024
#define LR_D 1024
#define LR_F 8192
#define LR_V4 (LR_D / 4)          // 256 float4 per row
#define ZCHUNK 128                // frames per zero-fill block
#define ZBLOCKS (LR_F / ZCHUNK)   // 64

__device__ int g_cum[LR_B * LR_T];   // inclusive cumsum of durations

// ---------------------------------------------------------------------------
// Kernel 1: per-batch inclusive scan (warp shuffles, 2 barriers) + durations
// pass-through (int -> float) fused in.
// ---------------------------------------------------------------------------
__global__ void lr_scan_kernel(const int* __restrict__ dur,
                               float* __restrict__ dur_out) {
    __shared__ int warp_sums[32];
    const int b    = blockIdx.x;
    const int t    = threadIdx.x;
    const int lane = t & 31;
    const int wid  = t >> 5;

    const int v = dur[b * LR_T + t];
    if (dur_out) dur_out[b * LR_T + t] = (float)v;

    // warp inclusive scan
    int s = v;
    #pragma unroll
    for (int o = 1; o < 32; o <<= 1) {
        int u = __shfl_up_sync(0xFFFFFFFFu, s, o);
        if (lane >= o) s += u;
    }
    if (lane == 31) warp_sums[wid] = s;
    __syncthreads();

    // warp 0 scans the 32 warp sums
    if (wid == 0) {
        int ws = warp_sums[lane];
        #pragma unroll
        for (int o = 1; o < 32; o <<= 1) {
            int u = __shfl_up_sync(0xFFFFFFFFu, ws, o);
            if (lane >= o) ws += u;
        }
        warp_sums[lane] = ws;
    }
    __syncthreads();

    const int prefix = (wid > 0) ? warp_sums[wid - 1] : 0;
    g_cum[b * LR_T + t] = s + prefix;
}

// ---------------------------------------------------------------------------
// Kernel 2: fused expand + zero-fill.
//   blockIdx.x <  LR_T        : token block t — load x row once, store dur[t]x
//   blockIdx.x >= LR_T        : zero block  — fill invalid frames in a chunk
// 256 threads; each thread owns one float4 column of the 4KB row.
// ---------------------------------------------------------------------------
__global__ void lr_expand_kernel(const float* __restrict__ x,
                                 const int* __restrict__ dur,
                                 float* __restrict__ out) {
    const int b = blockIdx.y;
    const int i = threadIdx.x;  // 0..255

    if (blockIdx.x < LR_T) {
        // ---- token path ----
        const int t = blockIdx.x;
        const int d = dur[b * LR_T + t];          // broadcast, L2 hit
        if (d == 0) return;
        const int end   = g_cum[b * LR_T + t];
        const int start = end - d;

        const float4 v = reinterpret_cast<const float4*>(x)
                             [((size_t)b * LR_T + t) * LR_V4 + i];
        float4* o = reinterpret_cast<float4*>(out) +
                    ((size_t)b * LR_F + start) * LR_V4 + i;
        #pragma unroll
        for (int k = 0; k < 8; ++k) {             // DMAX-1 max writes bound
            if (k < d) o[(size_t)k * LR_V4] = v;
        }
    } else {
        // ---- zero-fill path ----
        const int chunk = blockIdx.x - LR_T;
        const int total = g_cum[b * LR_T + (LR_T - 1)];
        const int f0 = chunk * ZCHUNK;
        const int f1 = f0 + ZCHUNK;
        int fs = (f0 > total) ? f0 : total;       // first invalid frame in chunk
        if (fs >= f1) return;
        const float4 z = make_float4(0.f, 0.f, 0.f, 0.f);
        float4* o = reinterpret_cast<float4*>(out) +
                    ((size_t)b * LR_F + fs) * LR_V4 + i;
        for (int f = fs; f < f1; ++f, o += LR_V4) *o = z;
    }
}

extern "C" void kernel_launch(void* const* d_in, const int* in_sizes, int n_in,
                              void* d_out, int out_size) {
    const float* x   = (const float*)d_in[0];  // [B, T, D] fp32
    const int*   dur = (const int*)  d_in[1];  // [B, T] int32
    float* out = (float*)d_out;

    const long long padded_elems = (long long)LR_B * LR_F * LR_D;
    float* dur_out =
        ((long long)out_size >= padded_elems + (long long)LR_B * LR_T)
            ? out + padded_elems : nullptr;

    lr_scan_kernel<<<LR_B, LR_T>>>(dur, dur_out);

    dim3 grid(LR_T + ZBLOCKS, LR_B);
    lr_expand_kernel<<<grid, LR_V4>>>(x, dur, out);
}